// round 4
// baseline (speedup 1.0000x reference)
#include <cuda_runtime.h>
#include <math.h>

// ---------------------------------------------------------------------------
#define FMP     40
#define HW      1600
#define BPC     5
#define NBOX    8000
#define NCLS    80
#define KDIM    512
#define MCOLS   432
#define CONF_TH 0.3f
#define NMS_TH  0.5f

#define OUT_SCORE  32000
#define OUT_LABEL  40000
#define OUT_KEEP   48000

__constant__ float c_anchor_w[5] = {17.f, 55.f, 92.f, 202.f, 289.f};
__constant__ float c_anchor_h[5] = {25.f, 75.f, 206.f, 21.f, 311.f};

__device__ float g_outmat[HW * MCOLS];   // [cell][col]: 0..399 cls, 400..404 obj, 405..424 reg, pad to 432
__device__ float g_b2[NBOX * 4];
__device__ float g_score[NBOX];
__device__ int   g_cls_count[NCLS];
__device__ int   g_cls_list[NCLS * NBOX];

typedef unsigned long long ull;

__device__ __forceinline__ void ffma2(ull& d, ull a, ull b) {
    asm("fma.rn.f32x2 %0, %1, %2, %0;" : "+l"(d) : "l"(a), "l"(b));
}
__device__ __forceinline__ float2 unpk(ull v) {
    float2 f; asm("mov.b64 {%0, %1}, %2;" : "=f"(f.x), "=f"(f.y) : "l"(v)); return f;
}
__device__ __forceinline__ float sigmoidf_(float x) { return 1.f / (1.f + expf(-x)); }

// ---------------------------------------------------------------------------
// GEMM (f32x2), occupancy-oriented: tile M32 x N32, BK=16, 128 threads,
// thread tile 2m x 4n. Grid (50 n-tiles, 14 m-tiles) = 700 blocks.
// m-tiles 0..12: w_cls rows 0..399 (tile 12 half-empty, writes ONLY m<400).
// m-tile 13: obj/reg rows -> cols 400..431 (sole owner of those columns).
__global__ __launch_bounds__(128) void gemm_kernel(
    const float* __restrict__ cls_feat, const float* __restrict__ reg_feat,
    const float* __restrict__ w_obj, const float* __restrict__ b_obj,
    const float* __restrict__ w_cls, const float* __restrict__ b_cls,
    const float* __restrict__ w_reg, const float* __restrict__ b_reg)
{
    __shared__ float sA[2][16][64];     // [buf][k][2*m] duplicated pairs
    __shared__ float sB[2][16][32];     // [buf][k][n]

    const int bx = blockIdx.x;          // n-tile (0..49)
    const int by = blockIdx.y;          // m-tile (0..13)
    const int tid = threadIdx.x;
    const int tx = tid & 7;             // n-group: 4n each
    const int ty = tid >> 3;            // m-group: 2m each
    const int n0 = bx * 32;

    if (bx == 0 && by == 0 && tid < NCLS) g_cls_count[tid] = 0;

    const float* F = (by < 13) ? cls_feat : reg_feat;
    const int mbase = by * 32;

    // A-load: thread t loads float4 (4 k) of one weight row
    const int am = tid >> 2;            // 0..31 m-within-tile
    const int ak4 = (tid & 3) * 4;      // k offset 0/4/8/12
    const float* aptr = nullptr;
    {
        if (by < 13) { int gm = mbase + am; if (gm < 400) aptr = w_cls + gm * KDIM; }
        else {
            int r = am;
            if (r < 5)       aptr = w_obj + r * KDIM;
            else if (r < 25) aptr = w_reg + (r - 5) * KDIM;
        }
    }

    const int bk = tid >> 3;            // 0..15
    const int bn4 = (tid & 7) * 4;

    float4 ra, rb;
    auto load_ab = [&](int k0) {
        ra = aptr ? *(const float4*)(aptr + k0 + ak4) : make_float4(0.f, 0.f, 0.f, 0.f);
        rb = *(const float4*)(F + (k0 + bk) * HW + n0 + bn4);
    };
    auto store_ab = [&](int p) {
        ((float2*)&sA[p][ak4 + 0][am * 2])[0] = make_float2(ra.x, ra.x);
        ((float2*)&sA[p][ak4 + 1][am * 2])[0] = make_float2(ra.y, ra.y);
        ((float2*)&sA[p][ak4 + 2][am * 2])[0] = make_float2(ra.z, ra.z);
        ((float2*)&sA[p][ak4 + 3][am * 2])[0] = make_float2(ra.w, ra.w);
        *(float4*)&sB[p][bk][bn4] = rb;
    };

    ull acc00 = 0, acc01 = 0, acc10 = 0, acc11 = 0;

    load_ab(0);
    store_ab(0);
    __syncthreads();
    int p = 0;
    for (int kb = 1; kb <= 32; kb++) {
        if (kb < 32) load_ab(kb * 16);
#pragma unroll
        for (int k = 0; k < 16; k++) {
            ulonglong2 av = *(const ulonglong2*)&sA[p][k][ty * 4]; // (m dup, m+1 dup)
            ulonglong2 bv = *(const ulonglong2*)&sB[p][k][tx * 4]; // (n,n+1),(n+2,n+3)
            ffma2(acc00, av.x, bv.x);
            ffma2(acc01, av.x, bv.y);
            ffma2(acc10, av.y, bv.x);
            ffma2(acc11, av.y, bv.y);
        }
        if (kb < 32) { store_ab(p ^ 1); __syncthreads(); p ^= 1; }
    }

    // epilogue — STRICT column ownership:
    //   by < 13 writes only cols < 400; by == 13 writes cols 400..431.
    int m0;
    float bv0, bv1;
    bool wvalid;
    {
        int lm = ty * 2;
        if (by < 13) {
            m0 = mbase + lm;
            wvalid = (m0 < 400);                    // m0 even; 400 boundary aligned
            bv0 = wvalid ? b_cls[m0] : 0.f;
            bv1 = wvalid ? b_cls[m0 + 1] : 0.f;
        } else {
            int r = lm;                              // 0..30 even
            m0 = 400 + r;                            // cols 400..431 (425..431 pad)
            wvalid = true;
            bv0 = (r < 5) ? b_obj[r] : (r < 25 ? b_reg[r - 5] : 0.f);
            int r1 = r + 1;
            bv1 = (r1 < 5) ? b_obj[r1] : (r1 < 25 ? b_reg[r1 - 5] : 0.f);
        }
    }
    if (wvalid) {
        int nb = n0 + tx * 4;
        float2 c00 = unpk(acc00), c01 = unpk(acc01);
        float2 c10 = unpk(acc10), c11 = unpk(acc11);
        *(float2*)&g_outmat[(nb + 0) * MCOLS + m0] = make_float2(c00.x + bv0, c10.x + bv1);
        *(float2*)&g_outmat[(nb + 1) * MCOLS + m0] = make_float2(c00.y + bv0, c10.y + bv1);
        *(float2*)&g_outmat[(nb + 2) * MCOLS + m0] = make_float2(c01.x + bv0, c11.x + bv1);
        *(float2*)&g_outmat[(nb + 3) * MCOLS + m0] = make_float2(c01.y + bv0, c11.y + bv1);
    }
}

// ---------------------------------------------------------------------------
// Decode: 4 threads per box, float4 scans, shfl argmax (first-max semantics).
__global__ __launch_bounds__(256) void box_kernel(float* __restrict__ dout) {
    int t = blockIdx.x * 256 + threadIdx.x;   // 32000 threads
    int i = t >> 2;
    int q = t & 3;
    int cell = i / BPC;
    int a    = i - cell * BPC;
    const float* row = g_outmat + cell * MCOLS;
    const float* cl  = row + a * NCLS + q * 20;

    float best = -1e30f; int bi = 0;
#pragma unroll
    for (int v = 0; v < 5; v++) {
        float4 f = *(const float4*)(cl + v * 4);
        int c0 = q * 20 + v * 4;
        if (f.x > best) { best = f.x; bi = c0; }
        if (f.y > best) { best = f.y; bi = c0 + 1; }
        if (f.z > best) { best = f.z; bi = c0 + 2; }
        if (f.w > best) { best = f.w; bi = c0 + 3; }
    }
#pragma unroll
    for (int off = 1; off < 4; off <<= 1) {
        float ov = __shfl_xor_sync(0xffffffffu, best, off);
        int   oi = __shfl_xor_sync(0xffffffffu, bi, off);
        if (ov > best || (ov == best && oi < bi)) { best = ov; bi = oi; }
    }
    if (q != 0) return;

    float obj   = row[400 + a];
    float score = sqrtf(sigmoidf_(obj) * sigmoidf_(best));

    float txv = row[405 + a * 4 + 0];
    float tyv = row[405 + a * 4 + 1];
    float twv = row[405 + a * 4 + 2];
    float thv = row[405 + a * 4 + 3];

    float ax = (float)(cell % FMP);
    float ay = (float)(cell / FMP);
    float cx = (sigmoidf_(txv) + ax) * 32.f;
    float cy = (sigmoidf_(tyv) + ay) * 32.f;
    float w  = expf(twv) * c_anchor_w[a];
    float h  = expf(thv) * c_anchor_h[a];

    float x1 = cx - 0.5f * w, y1 = cy - 0.5f * h;
    float x2 = cx + 0.5f * w, y2 = cy + 0.5f * h;

    *(float4*)(dout + i * 4) = make_float4(x1, y1, x2, y2);
    dout[OUT_SCORE + i] = score;
    dout[OUT_LABEL + i] = (float)bi;

    *(float4*)(g_b2 + i * 4) = make_float4(x1 - 0.5f * x2, y1 - 0.5f * y2,
                                           x1 + 0.5f * x2, y1 + 0.5f * y2);
    g_score[i] = score;

    int slot = atomicAdd(&g_cls_count[bi], 1);
    g_cls_list[bi * NBOX + slot] = i;
}

// ---------------------------------------------------------------------------
// Per-class NMS. Fast path (n <= 512): rank-sort + IoU bitmatrix + warp greedy.
#define NMS_SMEM 136000
#define NMS_CAP  512

__global__ __launch_bounds__(256) void nms_kernel(float* __restrict__ dout) {
    extern __shared__ char smem[];
    const int c = blockIdx.x;
    const int n = g_cls_count[c];
    const int* list = g_cls_list + c * NBOX;
    const int tid = threadIdx.x;

    if (n <= NMS_CAP) {
        int*      s_lg = (int*)smem;
        float*    s_ls = (float*)(smem + 2048);
        int*      s_si = (int*)(smem + 4096);
        float*    s_ss = (float*)(smem + 6144);
        float*    s_x1 = (float*)(smem + 8192);
        float*    s_y1 = (float*)(smem + 10240);
        float*    s_x2 = (float*)(smem + 12288);
        float*    s_y2 = (float*)(smem + 14336);
        float*    s_ar = (float*)(smem + 16384);
        unsigned* s_vb = (unsigned*)(smem + 18432);
        unsigned* s_sw = (unsigned*)(smem + 18496);
        unsigned* s_M  = (unsigned*)(smem + 18560);
        const int W = (n + 31) >> 5;

        for (int t = tid; t < n; t += 256) { int gi = list[t]; s_lg[t] = gi; s_ls[t] = g_score[gi]; }
        if (tid < 16) s_vb[tid] = 0u;
        __syncthreads();

        for (int t = tid; t < n; t += 256) {
            float st = s_ls[t]; int gt = s_lg[t]; int r = 0;
            for (int j = 0; j < n; j++) {
                float sj = s_ls[j];
                r += (sj > st) || (sj == st && s_lg[j] < gt);
            }
            s_si[r] = gt; s_ss[r] = st;
            float x1 = g_b2[gt * 4 + 0], y1 = g_b2[gt * 4 + 1];
            float x2 = g_b2[gt * 4 + 2], y2 = g_b2[gt * 4 + 3];
            s_x1[r] = x1; s_y1[r] = y1; s_x2[r] = x2; s_y2[r] = y2;
            s_ar[r] = (x2 - x1) * (y2 - y1);
            if (st >= CONF_TH) atomicOr(&s_vb[r >> 5], 1u << (r & 31));
        }
        __syncthreads();

        for (int t = tid; t < n * W; t += 256) {
            int k = t / W, w = t - k * W;
            float kx1 = s_x1[k], ky1 = s_y1[k], kx2 = s_x2[k], ky2 = s_y2[k], ka = s_ar[k];
            unsigned bits = 0;
            int jbase = w * 32;
            int jend = min(jbase + 32, n);
            for (int j = max(jbase, k + 1); j < jend; j++) {
                float xx1 = fmaxf(kx1, s_x1[j]);
                float yy1 = fmaxf(ky1, s_y1[j]);
                float xx2 = fminf(kx2, s_x2[j]);
                float yy2 = fminf(ky2, s_y2[j]);
                float inter = fmaxf(1e-10f, xx2 - xx1) * fmaxf(1e-10f, yy2 - yy1);
                float iou = inter / (ka + s_ar[j] - inter + 1e-14f);
                if (iou > NMS_TH) bits |= 1u << (j & 31);
            }
            s_M[k * W + w] = bits;
        }
        __syncthreads();

        if (tid < 32) {
            unsigned live = (tid < W) ? s_vb[tid] : 0u;
            for (int k = 0; k < n; k++) {
                unsigned lw = __shfl_sync(0xffffffffu, live, k >> 5);
                if (lw & (1u << (k & 31))) {
                    if (tid < W) live &= ~s_M[k * W + tid];
                }
            }
            if (tid < 16) s_sw[tid] = (tid < W) ? live : 0u;
        }
        __syncthreads();

        for (int t = tid; t < n; t += 256) {
            float kv = ((s_sw[t >> 5] >> (t & 31)) & 1u) ? 1.f : 0.f;
            dout[OUT_KEEP + s_si[t]] = kv;
        }
    } else {
        float* s_ls = (float*)smem;
        int*   s_lg = (int*)(smem + 32000);
        int*   s_si = (int*)(smem + 64000);
        float* s_ss = (float*)(smem + 96000);
        unsigned char* s_supp = (unsigned char*)(smem + 128000);

        for (int t = tid; t < n; t += 256) {
            int gi = list[t];
            s_lg[t] = gi; s_ls[t] = g_score[gi];
        }
        __syncthreads();
        for (int t = tid; t < n; t += 256) {
            float st = s_ls[t]; int gt = s_lg[t]; int r = 0;
            for (int j = 0; j < n; j++) {
                float sj = s_ls[j];
                r += (sj > st) || (sj == st && s_lg[j] < gt);
            }
            s_si[r] = gt; s_ss[r] = st;
        }
        for (int t = tid; t < n; t += 256) s_supp[t] = 0;
        __syncthreads();

        for (int k = 0; k < n; k++) {
            if (!s_supp[k] && s_ss[k] >= CONF_TH) {
                int gk = s_si[k];
                float bx1 = g_b2[gk * 4 + 0], by1 = g_b2[gk * 4 + 1];
                float bx2 = g_b2[gk * 4 + 2], by2 = g_b2[gk * 4 + 3];
                float ak = (bx2 - bx1) * (by2 - by1);
                for (int j = k + 1 + tid; j < n; j += 256) {
                    if (s_supp[j]) continue;
                    int gj = s_si[j];
                    float cx1 = g_b2[gj * 4 + 0], cy1 = g_b2[gj * 4 + 1];
                    float cx2 = g_b2[gj * 4 + 2], cy2 = g_b2[gj * 4 + 3];
                    float xx1 = fmaxf(bx1, cx1);
                    float yy1 = fmaxf(by1, cy1);
                    float xx2 = fminf(bx2, cx2);
                    float yy2 = fminf(by2, cy2);
                    float inter = fmaxf(1e-10f, xx2 - xx1) * fmaxf(1e-10f, yy2 - yy1);
                    float aj = (cx2 - cx1) * (cy2 - cy1);
                    float iou = inter / (ak + aj - inter + 1e-14f);
                    if (iou > NMS_TH) s_supp[j] = 1;
                }
            }
            __syncthreads();
        }
        for (int t = tid; t < n; t += 256) {
            float kv = (s_ss[t] >= CONF_TH && !s_supp[t]) ? 1.f : 0.f;
            dout[OUT_KEEP + s_si[t]] = kv;
        }
    }
}

// ---------------------------------------------------------------------------
extern "C" void kernel_launch(void* const* d_in, const int* in_sizes, int n_in,
                              void* d_out, int out_size) {
    const float* cls_feat = (const float*)d_in[0];
    const float* reg_feat = (const float*)d_in[1];
    const float* w_obj    = (const float*)d_in[2];
    const float* b_obj    = (const float*)d_in[3];
    const float* w_cls    = (const float*)d_in[4];
    const float* b_cls    = (const float*)d_in[5];
    const float* w_reg    = (const float*)d_in[6];
    const float* b_reg    = (const float*)d_in[7];
    float* out = (float*)d_out;

    cudaFuncSetAttribute(nms_kernel, cudaFuncAttributeMaxDynamicSharedMemorySize, NMS_SMEM);

    gemm_kernel<<<dim3(50, 14), 128>>>(cls_feat, reg_feat, w_obj, b_obj,
                                       w_cls, b_cls, w_reg, b_reg);
    box_kernel<<<125, 256>>>(out);
    nms_kernel<<<NCLS, 256, NMS_SMEM>>>(out);
}